// round 4
// baseline (speedup 1.0000x reference)
#include <cuda_runtime.h>
#include <math.h>

// Problem constants
#define B_    32
#define N_    256
#define E_    1024
#define T_    5
#define ANNO_ 18
#define ND_   64
#define VD_   64
#define AACT_ 3
#define BN_   8192
#define DEC_IN_ 1216   // E + ND + 2*VD

// ---------------- scratch (static device globals; no allocation) -------------
__device__ float g_h[BN_ * E_];            // encoder hidden  [8192,1024]
__device__ float g_a[BN_ * 2 * E_];        // [a_out | a_in]  [8192,2048]
__device__ float g_gi[BN_ * 3 * E_];       // encoder gi      [8192,3072]
__device__ float g_gh[BN_ * 3 * E_];       // encoder gh      [8192,3072]
__device__ float g_concat[BN_ * DEC_IN_];  // decoder input   [8192,1216]
__device__ float g_gid[BN_ * 6 * E_];      // decoder gi      [8192,6144]
__device__ float g_mid[BN_ * E_];          // relu layer      [8192,1024]
__device__ float g_out3[BN_ * AACT_];      // pre-mask logits [8192,3]
__device__ float g_vn[B_ * VD_];
__device__ float g_va[B_ * VD_];
__device__ float g_maxv[B_];

// ---------------- generic 128x128x8 SGEMM ------------------------------------
// Computes C = A * op(B) (+bias) (+relu), A row-major [M,K].
// B_NK=true : B row-major [N,K]  -> C = A * B^T   (weight GEMMs)
// B_NK=false: B row-major [K,N]  -> C = A * B     (adjacency GEMMs)
// blockIdx.z batches with byte-free element strides sA/sB/sC.
template <bool B_NK>
__global__ __launch_bounds__(256)
void sgemm_kernel(const float* __restrict__ Ab, const float* __restrict__ Bb,
                  float* __restrict__ Cb, const float* __restrict__ bias,
                  int K, int Nld, int ldc, int doRelu,
                  long long sA, long long sB, long long sC)
{
    const float* A = Ab + (long long)blockIdx.z * sA;
    const float* Bp = Bb + (long long)blockIdx.z * sB;
    float* C = Cb + (long long)blockIdx.z * sC;

    __shared__ float As[8][128];
    __shared__ float Bs[8][128];

    const int tid  = threadIdx.x;
    const int row0 = blockIdx.y * 128;
    const int col0 = blockIdx.x * 128;

    const int arow = tid >> 1;            // 0..127
    const int acol = (tid & 1) << 2;      // 0 or 4
    const int brow = tid >> 5;            // 0..7   (NN path)
    const int bcol = (tid & 31) << 2;     // 0..124 (NN path)

    const int ty = tid >> 4;              // 0..15
    const int tx = tid & 15;              // 0..15

    float acc[8][8];
#pragma unroll
    for (int i = 0; i < 8; i++)
#pragma unroll
        for (int j = 0; j < 8; j++) acc[i][j] = 0.f;

    for (int k0 = 0; k0 < K; k0 += 8) {
        float4 av = *(const float4*)(A + (long long)(row0 + arow) * K + k0 + acol);
        As[acol + 0][arow] = av.x;
        As[acol + 1][arow] = av.y;
        As[acol + 2][arow] = av.z;
        As[acol + 3][arow] = av.w;
        if constexpr (B_NK) {
            float4 bv = *(const float4*)(Bp + (long long)(col0 + arow) * K + k0 + acol);
            Bs[acol + 0][arow] = bv.x;
            Bs[acol + 1][arow] = bv.y;
            Bs[acol + 2][arow] = bv.z;
            Bs[acol + 3][arow] = bv.w;
        } else {
            float4 bv = *(const float4*)(Bp + (long long)(k0 + brow) * Nld + col0 + bcol);
            *(float4*)(&Bs[brow][bcol]) = bv;
        }
        __syncthreads();
#pragma unroll
        for (int k = 0; k < 8; k++) {
            float ra[8], rb[8];
            *(float4*)&ra[0] = *(const float4*)&As[k][ty * 4];
            *(float4*)&ra[4] = *(const float4*)&As[k][64 + ty * 4];
            *(float4*)&rb[0] = *(const float4*)&Bs[k][tx * 4];
            *(float4*)&rb[4] = *(const float4*)&Bs[k][64 + tx * 4];
#pragma unroll
            for (int i = 0; i < 8; i++)
#pragma unroll
                for (int j = 0; j < 8; j++)
                    acc[i][j] = fmaf(ra[i], rb[j], acc[i][j]);
        }
        __syncthreads();
    }

#pragma unroll
    for (int i = 0; i < 8; i++) {
        int r = row0 + ((i < 4) ? (ty * 4 + i) : (64 + ty * 4 + i - 4));
#pragma unroll
        for (int j = 0; j < 8; j += 4) {
            int c = col0 + ((j < 4) ? (tx * 4) : (64 + tx * 4));
            float4 v;
            v.x = acc[i][j + 0]; v.y = acc[i][j + 1];
            v.z = acc[i][j + 2]; v.w = acc[i][j + 3];
            if (bias) { v.x += bias[c]; v.y += bias[c + 1]; v.z += bias[c + 2]; v.w += bias[c + 3]; }
            if (doRelu) {
                v.x = fmaxf(v.x, 0.f); v.y = fmaxf(v.y, 0.f);
                v.z = fmaxf(v.z, 0.f); v.w = fmaxf(v.w, 0.f);
            }
            *(float4*)(C + (long long)r * ldc + c) = v;
        }
    }
}

// ---------------- small fused kernels ----------------------------------------

// h = annotation[BN,18] @ anno_W[18,1024]
__global__ void k_embed(const float* __restrict__ anno, const float* __restrict__ W)
{
    int r = blockIdx.x;
    __shared__ float arow[ANNO_];
    if (threadIdx.x < ANNO_) arow[threadIdx.x] = anno[r * ANNO_ + threadIdx.x];
    __syncthreads();
    for (int e = threadIdx.x; e < E_; e += blockDim.x) {
        float s = 0.f;
#pragma unroll
        for (int k = 0; k < ANNO_; k++) s = fmaf(arow[k], W[k * E_ + e], s);
        g_h[(long long)r * E_ + e] = s;
    }
}

__device__ __forceinline__ float sigmoidf_(float x) { return 1.f / (1.f + expf(-x)); }

// encoder GRU elementwise update (in place on g_h)
__global__ void k_gru()
{
    long long idx = (long long)blockIdx.x * 256 + threadIdx.x;  // r*1024 + e
    int r = (int)(idx >> 10);
    int e = (int)(idx & 1023);
    const float* gi = g_gi + (long long)r * 3072;
    const float* gh = g_gh + (long long)r * 3072;
    float rr = sigmoidf_(gi[e] + gh[e]);
    float zz = sigmoidf_(gi[1024 + e] + gh[1024 + e]);
    float nn = tanhf(gi[2048 + e] + rr * gh[2048 + e]);
    float hold = g_h[idx];
    g_h[idx] = (1.f - zz) * nn + zz * hold;
}

// vn = vnf_now @ vnf_now_W ; va = vnf_all @ vnf_all_W   (tiny)
__global__ void k_vnf(const float* __restrict__ vnow, const float* __restrict__ vall,
                      const float* __restrict__ Wn, const float* __restrict__ Wa)
{
    int b = blockIdx.x;
    int d = threadIdx.x;  // 64
    float sn = 0.f, sa = 0.f;
#pragma unroll
    for (int k = 0; k < 16; k++) {
        sn = fmaf(vnow[b * 16 + k], Wn[k * 64 + d], sn);
        sa = fmaf(vall[b * 16 + k], Wa[k * 64 + d], sa);
    }
    g_vn[b * 64 + d] = sn;
    g_va[b * 64 + d] = sa;
}

// concat_input = [enc_out | npos | va | vn]
__global__ void k_concat(const int* __restrict__ from_node, const float* __restrict__ pos_enc)
{
    int r = blockIdx.x;
    int b = r >> 8;
    float* dst = g_concat + (long long)r * DEC_IN_;
    const float* hs = g_h + (long long)r * E_;
    for (int i = threadIdx.x; i < E_; i += blockDim.x) dst[i] = hs[i];
    int fn = from_node[b];
    for (int i = threadIdx.x; i < 64; i += blockDim.x) {
        dst[1024 + i] = pos_enc[fn * 64 + i];
        dst[1088 + i] = g_va[b * 64 + i];
        dst[1152 + i] = g_vn[b * 64 + i];
    }
}

// decoder GRU with h0 = 0  =>  gh = bhh exactly; hidden = (1-z)*n
__global__ void k_decgru(const float* __restrict__ bhh, float* __restrict__ hidden_out)
{
    long long idx = (long long)blockIdx.x * 256 + threadIdx.x;  // r*2048 + e
    int r = (int)(idx >> 11);
    int e = (int)(idx & 2047);
    const float* gi = g_gid + (long long)r * 6144;
    float rr = sigmoidf_(gi[e] + bhh[e]);
    float zz = sigmoidf_(gi[2048 + e] + bhh[2048 + e]);
    float nn = tanhf(gi[4096 + e] + rr * bhh[4096 + e]);
    hidden_out[idx] = (1.f - zz) * nn;
}

// out3 = mid @ out_W2^T + b2   (thin N=3; one warp per row)
__global__ void k_out2(const float* __restrict__ W2, const float* __restrict__ b2)
{
    __shared__ float w[3][1024];
    int tid = threadIdx.x;
    for (int i = tid; i < 3 * 1024; i += 256) w[i >> 10][i & 1023] = W2[i];
    __syncthreads();
    int warp = tid >> 5, lane = tid & 31;
    int r = blockIdx.x * 8 + warp;
    const float* m = g_mid + (long long)r * 1024;
    float s0 = 0.f, s1 = 0.f, s2 = 0.f;
    for (int k = lane; k < 1024; k += 32) {
        float mv = m[k];
        s0 = fmaf(mv, w[0][k], s0);
        s1 = fmaf(mv, w[1][k], s1);
        s2 = fmaf(mv, w[2][k], s2);
    }
#pragma unroll
    for (int off = 16; off; off >>= 1) {
        s0 += __shfl_down_sync(0xffffffffu, s0, off);
        s1 += __shfl_down_sync(0xffffffffu, s1, off);
        s2 += __shfl_down_sync(0xffffffffu, s2, off);
    }
    if (lane == 0) {
        g_out3[r * 3 + 0] = s0 + b2[0];
        g_out3[r * 3 + 1] = s1 + b2[1];
        g_out3[r * 3 + 2] = s2 + b2[2];
    }
}

// per-batch max over (N, A_ACT)
__global__ void k_max()
{
    int b = blockIdx.x;
    __shared__ float sm[256];
    float mx = -INFINITY;
    for (int i = threadIdx.x; i < N_ * AACT_; i += 256)
        mx = fmaxf(mx, g_out3[b * N_ * AACT_ + i]);
    sm[threadIdx.x] = mx;
    __syncthreads();
    for (int s = 128; s; s >>= 1) {
        if (threadIdx.x < s) sm[threadIdx.x] = fmaxf(sm[threadIdx.x], sm[threadIdx.x + s]);
        __syncthreads();
    }
    if (threadIdx.x == 0) g_maxv[b] = sm[0];
}

// subtract (max+1), mask, +1, scatter node/vnf logits
__global__ void k_final(const int* __restrict__ mask, float* __restrict__ out)
{
    int r = blockIdx.x * 256 + threadIdx.x;  // < 8192
    if (r >= BN_) return;
    int b = r >> 8;
    float mv = g_maxv[b] + 1.f;
    float mf = (mask[r] == 1) ? 1.f : 1e10f;
    float v0 = mf * (g_out3[r * 3 + 0] - mv) + 1.f;
    float v1 = mf * (g_out3[r * 3 + 1] - mv) + 1.f;
    float v2 = mf * (g_out3[r * 3 + 2] - mv) + 1.f;
    out[r] = v0;                      // node_logits [B,N]
    out[BN_ + r * 2 + 0] = v1;        // vnf_logits  [B,N,2]
    out[BN_ + r * 2 + 1] = v2;
}

// ---------------- launcher ----------------------------------------------------
extern "C" void kernel_launch(void* const* d_in, const int* in_sizes, int n_in,
                              void* d_out, int out_size)
{
    const float* annotation = (const float*)d_in[0];
    const float* A_out      = (const float*)d_in[1];
    const float* A_in       = (const float*)d_in[2];
    const int*   from_node  = (const int*)  d_in[3];
    const float* vnf_now    = (const float*)d_in[4];
    const float* vnf_all    = (const float*)d_in[5];
    const int*   mask       = (const int*)  d_in[6];
    const float* anno_W     = (const float*)d_in[7];
    const float* gru_Wih    = (const float*)d_in[8];
    const float* gru_Whh    = (const float*)d_in[9];
    const float* vnf_now_W  = (const float*)d_in[10];
    const float* vnf_all_W  = (const float*)d_in[11];
    const float* dgru_Wih   = (const float*)d_in[12];
    // d_in[13] = dgru_Whh: unused because h0 == 0 -> gh == dgru_bhh exactly
    const float* dgru_bih   = (const float*)d_in[14];
    const float* dgru_bhh   = (const float*)d_in[15];
    const float* out_W1     = (const float*)d_in[16];
    const float* out_b1     = (const float*)d_in[17];
    const float* out_W2     = (const float*)d_in[18];
    const float* out_b2     = (const float*)d_in[19];
    const float* pos_enc    = (const float*)d_in[20];

    float* out = (float*)d_out;
    float* hidden = out + BN_ + BN_ * 2;   // [8192,2048] region of d_out

    // device addresses of scratch symbols (query only; capture-legal)
    float *p_h, *p_a, *p_gi, *p_gh, *p_concat, *p_gid, *p_mid;
    cudaGetSymbolAddress((void**)&p_h, g_h);
    cudaGetSymbolAddress((void**)&p_a, g_a);
    cudaGetSymbolAddress((void**)&p_gi, g_gi);
    cudaGetSymbolAddress((void**)&p_gh, g_gh);
    cudaGetSymbolAddress((void**)&p_concat, g_concat);
    cudaGetSymbolAddress((void**)&p_gid, g_gid);
    cudaGetSymbolAddress((void**)&p_mid, g_mid);

    // 1) embedding
    k_embed<<<BN_, 256>>>(annotation, anno_W);

    // 2) T encoder GRU steps
    dim3 gAdj(E_ / 128, N_ / 128, B_);        // (8, 2, 32)
    dim3 gGi(3 * E_ / 128, BN_ / 128, 1);     // (24, 64)
    for (int t = 0; t < T_; t++) {
        // a_out = A_out[b] @ h[b]   -> cols [0,1024) of g_a
        sgemm_kernel<false><<<gAdj, 256>>>(A_out, p_h, p_a, nullptr,
                                           N_, E_, 2 * E_, 0,
                                           (long long)N_ * N_, (long long)N_ * E_,
                                           (long long)N_ * 2 * E_);
        // a_in  = A_in[b] @ h[b]    -> cols [1024,2048)
        sgemm_kernel<false><<<gAdj, 256>>>(A_in, p_h, p_a + E_, nullptr,
                                           N_, E_, 2 * E_, 0,
                                           (long long)N_ * N_, (long long)N_ * E_,
                                           (long long)N_ * 2 * E_);
        // gi = a @ gru_Wih^T        [8192,3072], K=2048
        sgemm_kernel<true><<<gGi, 256>>>(p_a, gru_Wih, p_gi, nullptr,
                                         2 * E_, 0, 3 * E_, 0, 0, 0, 0);
        // gh = h @ gru_Whh^T        [8192,3072], K=1024
        sgemm_kernel<true><<<gGi, 256>>>(p_h, gru_Whh, p_gh, nullptr,
                                         E_, 0, 3 * E_, 0, 0, 0, 0);
        // fused GRU update (in place)
        k_gru<<<BN_ * E_ / 256, 256>>>();
    }

    // 3) decoder input
    k_vnf<<<B_, 64>>>(vnf_now, vnf_all, vnf_now_W, vnf_all_W);
    k_concat<<<BN_, 256>>>(from_node, pos_enc);

    // 4) gi_dec = concat @ dgru_Wih^T + bih   [8192,6144], K=1216
    dim3 gGid(6 * E_ / 128, BN_ / 128, 1);    // (48, 64)
    sgemm_kernel<true><<<gGid, 256>>>(p_concat, dgru_Wih, p_gid, dgru_bih,
                                      DEC_IN_, 0, 6 * E_, 0, 0, 0, 0);

    // 5) hidden = (1-z)*n  (h0 == 0; gh == bhh) — written straight into d_out
    k_decgru<<<BN_ * 2 * E_ / 256, 256>>>(dgru_bhh, hidden);

    // 6) mid = relu(hidden @ out_W1^T + b1)   [8192,1024], K=2048
    dim3 gMid(E_ / 128, BN_ / 128, 1);        // (8, 64)
    sgemm_kernel<true><<<gMid, 256>>>(hidden, out_W1, p_mid, out_b1,
                                      2 * E_, 0, E_, 1, 0, 0, 0);

    // 7) thin head + max + mask/scatter
    k_out2<<<BN_ / 8, 256>>>(out_W2, out_b2);
    k_max<<<B_, 256>>>();
    k_final<<<BN_ / 256, 256>>>(mask, out);
}

// round 5
// speedup vs baseline: 1.0003x; 1.0003x over previous
#include <cuda_runtime.h>
#include <math.h>

// Problem constants
#define B_    32
#define N_    256
#define E_    1024
#define T_    5
#define ANNO_ 18
#define ND_   64
#define VD_   64
#define AACT_ 3
#define BN_   8192
#define DEC_IN_ 1216   // E + ND + 2*VD

// ---------------- scratch (static device globals; no allocation) -------------
__device__ float g_h[BN_ * E_];            // encoder hidden  [8192,1024]
__device__ float g_a[BN_ * 2 * E_];        // [a_out | a_in]  [8192,2048]
__device__ float g_gi[BN_ * 3 * E_];       // encoder gi      [8192,3072]
__device__ float g_gh[BN_ * 3 * E_];       // encoder gh      [8192,3072]
__device__ float g_concat[BN_ * DEC_IN_];  // decoder input   [8192,1216]
__device__ float g_gid[BN_ * 6 * E_];      // decoder gi      [8192,6144]
__device__ float g_mid[BN_ * E_];          // relu layer      [8192,1024]
__device__ float g_out3[BN_ * AACT_];      // pre-mask logits [8192,3]
__device__ float g_vn[B_ * VD_];
__device__ float g_va[B_ * VD_];
__device__ float g_maxv[B_];

// ---------------- generic 128x128x8 SGEMM ------------------------------------
// Computes C = A * op(B) (+bias) (+relu), A row-major [M,K].
// B_NK=true : B row-major [N,K]  -> C = A * B^T   (weight GEMMs)
// B_NK=false: B row-major [K,N]  -> C = A * B     (adjacency GEMMs)
// blockIdx.z batches with byte-free element strides sA/sB/sC.
template <bool B_NK>
__global__ __launch_bounds__(256)
void sgemm_kernel(const float* __restrict__ Ab, const float* __restrict__ Bb,
                  float* __restrict__ Cb, const float* __restrict__ bias,
                  int K, int Nld, int ldc, int doRelu,
                  long long sA, long long sB, long long sC)
{
    const float* A = Ab + (long long)blockIdx.z * sA;
    const float* Bp = Bb + (long long)blockIdx.z * sB;
    float* C = Cb + (long long)blockIdx.z * sC;

    __shared__ float As[8][128];
    __shared__ float Bs[8][128];

    const int tid  = threadIdx.x;
    const int row0 = blockIdx.y * 128;
    const int col0 = blockIdx.x * 128;

    const int arow = tid >> 1;            // 0..127
    const int acol = (tid & 1) << 2;      // 0 or 4
    const int brow = tid >> 5;            // 0..7   (NN path)
    const int bcol = (tid & 31) << 2;     // 0..124 (NN path)

    const int ty = tid >> 4;              // 0..15
    const int tx = tid & 15;              // 0..15

    float acc[8][8];
#pragma unroll
    for (int i = 0; i < 8; i++)
#pragma unroll
        for (int j = 0; j < 8; j++) acc[i][j] = 0.f;

    for (int k0 = 0; k0 < K; k0 += 8) {
        float4 av = *(const float4*)(A + (long long)(row0 + arow) * K + k0 + acol);
        As[acol + 0][arow] = av.x;
        As[acol + 1][arow] = av.y;
        As[acol + 2][arow] = av.z;
        As[acol + 3][arow] = av.w;
        if constexpr (B_NK) {
            float4 bv = *(const float4*)(Bp + (long long)(col0 + arow) * K + k0 + acol);
            Bs[acol + 0][arow] = bv.x;
            Bs[acol + 1][arow] = bv.y;
            Bs[acol + 2][arow] = bv.z;
            Bs[acol + 3][arow] = bv.w;
        } else {
            float4 bv = *(const float4*)(Bp + (long long)(k0 + brow) * Nld + col0 + bcol);
            *(float4*)(&Bs[brow][bcol]) = bv;
        }
        __syncthreads();
#pragma unroll
        for (int k = 0; k < 8; k++) {
            float ra[8], rb[8];
            *(float4*)&ra[0] = *(const float4*)&As[k][ty * 4];
            *(float4*)&ra[4] = *(const float4*)&As[k][64 + ty * 4];
            *(float4*)&rb[0] = *(const float4*)&Bs[k][tx * 4];
            *(float4*)&rb[4] = *(const float4*)&Bs[k][64 + tx * 4];
#pragma unroll
            for (int i = 0; i < 8; i++)
#pragma unroll
                for (int j = 0; j < 8; j++)
                    acc[i][j] = fmaf(ra[i], rb[j], acc[i][j]);
        }
        __syncthreads();
    }

#pragma unroll
    for (int i = 0; i < 8; i++) {
        int r = row0 + ((i < 4) ? (ty * 4 + i) : (64 + ty * 4 + i - 4));
#pragma unroll
        for (int j = 0; j < 8; j += 4) {
            int c = col0 + ((j < 4) ? (tx * 4) : (64 + tx * 4));
            float4 v;
            v.x = acc[i][j + 0]; v.y = acc[i][j + 1];
            v.z = acc[i][j + 2]; v.w = acc[i][j + 3];
            if (bias) { v.x += bias[c]; v.y += bias[c + 1]; v.z += bias[c + 2]; v.w += bias[c + 3]; }
            if (doRelu) {
                v.x = fmaxf(v.x, 0.f); v.y = fmaxf(v.y, 0.f);
                v.z = fmaxf(v.z, 0.f); v.w = fmaxf(v.w, 0.f);
            }
            *(float4*)(C + (long long)r * ldc + c) = v;
        }
    }
}

// ---------------- small fused kernels ----------------------------------------

// h = annotation[BN,18] @ anno_W[18,1024]
__global__ void k_embed(const float* __restrict__ anno, const float* __restrict__ W)
{
    int r = blockIdx.x;
    __shared__ float arow[ANNO_];
    if (threadIdx.x < ANNO_) arow[threadIdx.x] = anno[r * ANNO_ + threadIdx.x];
    __syncthreads();
    for (int e = threadIdx.x; e < E_; e += blockDim.x) {
        float s = 0.f;
#pragma unroll
        for (int k = 0; k < ANNO_; k++) s = fmaf(arow[k], W[k * E_ + e], s);
        g_h[(long long)r * E_ + e] = s;
    }
}

__device__ __forceinline__ float sigmoidf_(float x) { return 1.f / (1.f + expf(-x)); }

// encoder GRU elementwise update (in place on g_h)
__global__ void k_gru()
{
    long long idx = (long long)blockIdx.x * 256 + threadIdx.x;  // r*1024 + e
    int r = (int)(idx >> 10);
    int e = (int)(idx & 1023);
    const float* gi = g_gi + (long long)r * 3072;
    const float* gh = g_gh + (long long)r * 3072;
    float rr = sigmoidf_(gi[e] + gh[e]);
    float zz = sigmoidf_(gi[1024 + e] + gh[1024 + e]);
    float nn = tanhf(gi[2048 + e] + rr * gh[2048 + e]);
    float hold = g_h[idx];
    g_h[idx] = (1.f - zz) * nn + zz * hold;
}

// vn = vnf_now @ vnf_now_W ; va = vnf_all @ vnf_all_W   (tiny)
__global__ void k_vnf(const float* __restrict__ vnow, const float* __restrict__ vall,
                      const float* __restrict__ Wn, const float* __restrict__ Wa)
{
    int b = blockIdx.x;
    int d = threadIdx.x;  // 64
    float sn = 0.f, sa = 0.f;
#pragma unroll
    for (int k = 0; k < 16; k++) {
        sn = fmaf(vnow[b * 16 + k], Wn[k * 64 + d], sn);
        sa = fmaf(vall[b * 16 + k], Wa[k * 64 + d], sa);
    }
    g_vn[b * 64 + d] = sn;
    g_va[b * 64 + d] = sa;
}

// concat_input = [enc_out | npos | va | vn]
__global__ void k_concat(const int* __restrict__ from_node, const float* __restrict__ pos_enc)
{
    int r = blockIdx.x;
    int b = r >> 8;
    float* dst = g_concat + (long long)r * DEC_IN_;
    const float* hs = g_h + (long long)r * E_;
    for (int i = threadIdx.x; i < E_; i += blockDim.x) dst[i] = hs[i];
    int fn = from_node[b];
    for (int i = threadIdx.x; i < 64; i += blockDim.x) {
        dst[1024 + i] = pos_enc[fn * 64 + i];
        dst[1088 + i] = g_va[b * 64 + i];
        dst[1152 + i] = g_vn[b * 64 + i];
    }
}

// decoder GRU with h0 = 0  =>  gh = bhh exactly; hidden = (1-z)*n
__global__ void k_decgru(const float* __restrict__ bhh, float* __restrict__ hidden_out)
{
    long long idx = (long long)blockIdx.x * 256 + threadIdx.x;  // r*2048 + e
    int r = (int)(idx >> 11);
    int e = (int)(idx & 2047);
    const float* gi = g_gid + (long long)r * 6144;
    float rr = sigmoidf_(gi[e] + bhh[e]);
    float zz = sigmoidf_(gi[2048 + e] + bhh[2048 + e]);
    float nn = tanhf(gi[4096 + e] + rr * bhh[4096 + e]);
    hidden_out[idx] = (1.f - zz) * nn;
}

// out3 = mid @ out_W2^T + b2   (thin N=3; one warp per row)
__global__ void k_out2(const float* __restrict__ W2, const float* __restrict__ b2)
{
    __shared__ float w[3][1024];
    int tid = threadIdx.x;
    for (int i = tid; i < 3 * 1024; i += 256) w[i >> 10][i & 1023] = W2[i];
    __syncthreads();
    int warp = tid >> 5, lane = tid & 31;
    int r = blockIdx.x * 8 + warp;
    const float* m = g_mid + (long long)r * 1024;
    float s0 = 0.f, s1 = 0.f, s2 = 0.f;
    for (int k = lane; k < 1024; k += 32) {
        float mv = m[k];
        s0 = fmaf(mv, w[0][k], s0);
        s1 = fmaf(mv, w[1][k], s1);
        s2 = fmaf(mv, w[2][k], s2);
    }
#pragma unroll
    for (int off = 16; off; off >>= 1) {
        s0 += __shfl_down_sync(0xffffffffu, s0, off);
        s1 += __shfl_down_sync(0xffffffffu, s1, off);
        s2 += __shfl_down_sync(0xffffffffu, s2, off);
    }
    if (lane == 0) {
        g_out3[r * 3 + 0] = s0 + b2[0];
        g_out3[r * 3 + 1] = s1 + b2[1];
        g_out3[r * 3 + 2] = s2 + b2[2];
    }
}

// per-batch max over (N, A_ACT)
__global__ void k_max()
{
    int b = blockIdx.x;
    __shared__ float sm[256];
    float mx = -INFINITY;
    for (int i = threadIdx.x; i < N_ * AACT_; i += 256)
        mx = fmaxf(mx, g_out3[b * N_ * AACT_ + i]);
    sm[threadIdx.x] = mx;
    __syncthreads();
    for (int s = 128; s; s >>= 1) {
        if (threadIdx.x < s) sm[threadIdx.x] = fmaxf(sm[threadIdx.x], sm[threadIdx.x + s]);
        __syncthreads();
    }
    if (threadIdx.x == 0) g_maxv[b] = sm[0];
}

// subtract (max+1), mask, +1, scatter node/vnf logits
__global__ void k_final(const int* __restrict__ mask, float* __restrict__ out)
{
    int r = blockIdx.x * 256 + threadIdx.x;  // < 8192
    if (r >= BN_) return;
    int b = r >> 8;
    float mv = g_maxv[b] + 1.f;
    float mf = (mask[r] == 1) ? 1.f : 1e10f;
    float v0 = mf * (g_out3[r * 3 + 0] - mv) + 1.f;
    float v1 = mf * (g_out3[r * 3 + 1] - mv) + 1.f;
    float v2 = mf * (g_out3[r * 3 + 2] - mv) + 1.f;
    out[r] = v0;                      // node_logits [B,N]
    out[BN_ + r * 2 + 0] = v1;        // vnf_logits  [B,N,2]
    out[BN_ + r * 2 + 1] = v2;
}

// ---------------- launcher ----------------------------------------------------
extern "C" void kernel_launch(void* const* d_in, const int* in_sizes, int n_in,
                              void* d_out, int out_size)
{
    const float* annotation = (const float*)d_in[0];
    const float* A_out      = (const float*)d_in[1];
    const float* A_in       = (const float*)d_in[2];
    const int*   from_node  = (const int*)  d_in[3];
    const float* vnf_now    = (const float*)d_in[4];
    const float* vnf_all    = (const float*)d_in[5];
    const int*   mask       = (const int*)  d_in[6];
    const float* anno_W     = (const float*)d_in[7];
    const float* gru_Wih    = (const float*)d_in[8];
    const float* gru_Whh    = (const float*)d_in[9];
    const float* vnf_now_W  = (const float*)d_in[10];
    const float* vnf_all_W  = (const float*)d_in[11];
    const float* dgru_Wih   = (const float*)d_in[12];
    // d_in[13] = dgru_Whh: unused because h0 == 0 -> gh == dgru_bhh exactly
    const float* dgru_bih   = (const float*)d_in[14];
    const float* dgru_bhh   = (const float*)d_in[15];
    const float* out_W1     = (const float*)d_in[16];
    const float* out_b1     = (const float*)d_in[17];
    const float* out_W2     = (const float*)d_in[18];
    const float* out_b2     = (const float*)d_in[19];
    const float* pos_enc    = (const float*)d_in[20];

    float* out = (float*)d_out;
    float* hidden = out + BN_ + BN_ * 2;   // [8192,2048] region of d_out

    // device addresses of scratch symbols (query only; capture-legal)
    float *p_h, *p_a, *p_gi, *p_gh, *p_concat, *p_gid, *p_mid;
    cudaGetSymbolAddress((void**)&p_h, g_h);
    cudaGetSymbolAddress((void**)&p_a, g_a);
    cudaGetSymbolAddress((void**)&p_gi, g_gi);
    cudaGetSymbolAddress((void**)&p_gh, g_gh);
    cudaGetSymbolAddress((void**)&p_concat, g_concat);
    cudaGetSymbolAddress((void**)&p_gid, g_gid);
    cudaGetSymbolAddress((void**)&p_mid, g_mid);

    // 1) embedding
    k_embed<<<BN_, 256>>>(annotation, anno_W);

    // 2) T encoder GRU steps
    dim3 gAdj(E_ / 128, N_ / 128, B_);        // (8, 2, 32)
    dim3 gGi(3 * E_ / 128, BN_ / 128, 1);     // (24, 64)
    for (int t = 0; t < T_; t++) {
        // a_out = A_out[b] @ h[b]   -> cols [0,1024) of g_a
        sgemm_kernel<false><<<gAdj, 256>>>(A_out, p_h, p_a, nullptr,
                                           N_, E_, 2 * E_, 0,
                                           (long long)N_ * N_, (long long)N_ * E_,
                                           (long long)N_ * 2 * E_);
        // a_in  = A_in[b] @ h[b]    -> cols [1024,2048)
        sgemm_kernel<false><<<gAdj, 256>>>(A_in, p_h, p_a + E_, nullptr,
                                           N_, E_, 2 * E_, 0,
                                           (long long)N_ * N_, (long long)N_ * E_,
                                           (long long)N_ * 2 * E_);
        // gi = a @ gru_Wih^T        [8192,3072], K=2048
        sgemm_kernel<true><<<gGi, 256>>>(p_a, gru_Wih, p_gi, nullptr,
                                         2 * E_, 0, 3 * E_, 0, 0, 0, 0);
        // gh = h @ gru_Whh^T        [8192,3072], K=1024
        sgemm_kernel<true><<<gGi, 256>>>(p_h, gru_Whh, p_gh, nullptr,
                                         E_, 0, 3 * E_, 0, 0, 0, 0);
        // fused GRU update (in place)
        k_gru<<<BN_ * E_ / 256, 256>>>();
    }

    // 3) decoder input
    k_vnf<<<B_, 64>>>(vnf_now, vnf_all, vnf_now_W, vnf_all_W);
    k_concat<<<BN_, 256>>>(from_node, pos_enc);

    // 4) gi_dec = concat @ dgru_Wih^T + bih   [8192,6144], K=1216
    dim3 gGid(6 * E_ / 128, BN_ / 128, 1);    // (48, 64)
    sgemm_kernel<true><<<gGid, 256>>>(p_concat, dgru_Wih, p_gid, dgru_bih,
                                      DEC_IN_, 0, 6 * E_, 0, 0, 0, 0);

    // 5) hidden = (1-z)*n  (h0 == 0; gh == bhh) — written straight into d_out
    k_decgru<<<BN_ * 2 * E_ / 256, 256>>>(dgru_bhh, hidden);

    // 6) mid = relu(hidden @ out_W1^T + b1)   [8192,1024], K=2048
    dim3 gMid(E_ / 128, BN_ / 128, 1);        // (8, 64)
    sgemm_kernel<true><<<gMid, 256>>>(hidden, out_W1, p_mid, out_b1,
                                      2 * E_, 0, E_, 1, 0, 0, 0);

    // 7) thin head + max + mask/scatter
    k_out2<<<BN_ / 8, 256>>>(out_W2, out_b2);
    k_max<<<B_, 256>>>();
    k_final<<<BN_ / 256, 256>>>(mask, out);
}

// round 7
// speedup vs baseline: 2.1011x; 2.1004x over previous
#include <cuda_runtime.h>
#include <cuda_bf16.h>
#include <math.h>
#include <stdint.h>

// Problem constants
#define B_    32
#define N_    256
#define E_    1024
#define T_    5
#define ANNO_ 18
#define AACT_ 3
#define BN_   8192
#define DEC_IN_ 1216   // E + ND + 2*VD

// ---------------- scratch (static device globals; no allocation) -------------
__device__ float g_h  [BN_ * E_];          // encoder hidden  [8192,1024]
__device__ float g_gi [BN_ * 3 * E_];      // encoder gi      [8192,3072]
__device__ float g_gh [BN_ * 3 * E_];      // encoder gh      [8192,3072]
__device__ float g_gid[BN_ * 6 * E_];      // decoder gi      [8192,6144]
__device__ float g_mid[BN_ * E_];          // relu layer      [8192,1024]
__device__ float g_out3[BN_ * AACT_];
__device__ float g_vn[B_ * 64];
__device__ float g_va[B_ * 64];
__device__ float g_maxv[B_];

// bf16 split operands (merged-K layouts)
__device__ __align__(256) __nv_bfloat16 g_Wihp [3072 * 6144];    // [hi|hi|lo] K=2048
__device__ __align__(256) __nv_bfloat16 g_Whhp [3072 * 3072];    // [hi|hi|lo] K=1024
__device__ __align__(256) __nv_bfloat16 g_dWihp[6144 * 3648];    // [hi|hi|lo] K=1216
__device__ __align__(256) __nv_bfloat16 g_W1p  [1024 * 6144];    // [hi|hi|lo] K=2048
__device__ __align__(256) __nv_bfloat16 g_adjO [B_ * 256 * 512]; // [A|A] exact
__device__ __align__(256) __nv_bfloat16 g_adjI [B_ * 256 * 512];
__device__ __align__(256) __nv_bfloat16 g_ap   [BN_ * 6144];     // a'  [hi|lo|hi] K=2048
__device__ __align__(256) __nv_bfloat16 g_hp   [BN_ * 3072];     // h'  [hi|lo|hi] K=1024
__device__ __align__(256) __nv_bfloat16 g_ht   [B_ * 1024 * 512];// h^T [hi|lo]    K=256x2
__device__ __align__(256) __nv_bfloat16 g_cp   [BN_ * 3648];     // concat' [hi|lo|hi]
__device__ __align__(256) __nv_bfloat16 g_hidp [BN_ * 6144];     // hidden' [hi|lo|hi]

// ---------------- helpers -----------------------------------------------------
__device__ __forceinline__ uint32_t s2u(const void* p) {
    uint32_t a;
    asm("{ .reg .u64 t; cvta.to.shared.u64 t, %1; cvt.u32.u64 %0, t; }" : "=r"(a) : "l"(p));
    return a;
}
__device__ __forceinline__ uint64_t g2u(const void* p) {
    uint64_t a;
    asm("cvta.to.global.u64 %0, %1;" : "=l"(a) : "l"(p));
    return a;
}

#define CP_ASYNC16(smem_u32, gptr64) \
    asm volatile("cp.async.cg.shared.global [%0], [%1], 16;" :: "r"(smem_u32), "l"(gptr64))
#define CP_COMMIT() asm volatile("cp.async.commit_group;" ::: "memory")
#define CP_WAIT(n)  asm volatile("cp.async.wait_group %0;" :: "n"(n) : "memory")

#define MMA16816(d, a, b)                                                     \
    asm volatile(                                                             \
        "mma.sync.aligned.m16n8k16.row.col.f32.bf16.bf16.f32 "                \
        "{%0,%1,%2,%3}, {%4,%5,%6,%7}, {%8,%9}, {%0,%1,%2,%3};"               \
        : "+f"((d)[0]), "+f"((d)[1]), "+f"((d)[2]), "+f"((d)[3])              \
        : "r"((a)[0]), "r"((a)[1]), "r"((a)[2]), "r"((a)[3]),                 \
          "r"((b)[0]), "r"((b)[1]))

// ---------------- mma.sync GEMM: C[M,N] = A[M,K'] * B[N,K']^T -----------------
// A,B bf16 row-major K-major. CTA tile 128x128, BK=32, 8 warps (warp 64x32).
// Padded SMEM pitch 40 bf16/row (conflict-free fragment loads).
// Epilogue: spl==null -> f32 (+bias)(+relu) into C;
//           spl!=null -> 3-way bf16 split [hi|lo|hi], pitch splPitch, sec width
//                        splK, column offset splColOff.
#define PITCH 40
#define STAGE_ELEM (128 * PITCH)

__global__ __launch_bounds__(256, 2)
void gemm_mma(const __nv_bfloat16* __restrict__ A, const __nv_bfloat16* __restrict__ Bm,
              int Kp, long long sA, long long sB,
              float* __restrict__ C, int ldc, long long sC,
              const float* __restrict__ bias, int relu,
              __nv_bfloat16* __restrict__ spl, int splPitch, int splK, int splColOff,
              long long sSpl)
{
    __shared__ __nv_bfloat16 As[2][STAGE_ELEM];
    __shared__ __nv_bfloat16 Bs[2][STAGE_ELEM];

    const int tid  = threadIdx.x;
    const int wid  = tid >> 5, lane = tid & 31;
    const int g    = lane >> 2, tig = lane & 3;
    const int wm0  = (wid & 1) * 64;
    const int wn0  = (wid >> 1) * 32;
    const int z    = blockIdx.z;

    const __nv_bfloat16* Ab = A  + (long long)z * sA + (long long)(blockIdx.y * 128) * Kp;
    const __nv_bfloat16* Bb = Bm + (long long)z * sB + (long long)(blockIdx.x * 128) * Kp;

    // per-thread cp.async coords: 512 16B-chunks per operand tile, 2/thread
    const int lr = tid >> 2;               // 0..63
    const int lc = (tid & 3) * 8;          // bf16 col of 16B chunk
    const uint64_t gA0 = g2u(Ab + (long long)lr * Kp + lc);
    const uint64_t gA1 = g2u(Ab + (long long)(lr + 64) * Kp + lc);
    const uint64_t gB0 = g2u(Bb + (long long)lr * Kp + lc);
    const uint64_t gB1 = g2u(Bb + (long long)(lr + 64) * Kp + lc);
    const uint32_t sA0 = s2u(&As[0][lr * PITCH + lc]);
    const uint32_t sA1 = sA0 + 64 * PITCH * 2;
    const uint32_t sB0 = s2u(&Bs[0][lr * PITCH + lc]);
    const uint32_t sB1 = sB0 + 64 * PITCH * 2;
    const uint32_t stB = STAGE_ELEM * 2;   // stage stride bytes

#define LOAD_STAGE(s, koffB)                                   \
    do {                                                       \
        CP_ASYNC16(sA0 + (s) * stB, gA0 + (koffB));            \
        CP_ASYNC16(sA1 + (s) * stB, gA1 + (koffB));            \
        CP_ASYNC16(sB0 + (s) * stB, gB0 + (koffB));            \
        CP_ASYNC16(sB1 + (s) * stB, gB1 + (koffB));            \
        CP_COMMIT();                                           \
    } while (0)

    float acc[4][4][4];
#pragma unroll
    for (int i = 0; i < 4; i++)
#pragma unroll
        for (int j = 0; j < 4; j++)
#pragma unroll
            for (int c = 0; c < 4; c++) acc[i][j][c] = 0.f;

    const int nIter = Kp >> 5;
    LOAD_STAGE(0, 0);

    for (int it = 0; it < nIter; ++it) {
        if (it + 1 < nIter) {
            LOAD_STAGE((it + 1) & 1, (long long)(it + 1) * 64);
            CP_WAIT(1);
        } else {
            CP_WAIT(0);
        }
        __syncthreads();

        const __nv_bfloat16* as = As[it & 1];
        const __nv_bfloat16* bs = Bs[it & 1];
#pragma unroll
        for (int ks = 0; ks < 32; ks += 16) {
            uint32_t af[4][4], bf[4][2];
#pragma unroll
            for (int i = 0; i < 4; i++) {
                const __nv_bfloat16* p = as + (wm0 + i * 16 + g) * PITCH + ks + tig * 2;
                af[i][0] = *(const uint32_t*)p;
                af[i][1] = *(const uint32_t*)(p + 8 * PITCH);
                af[i][2] = *(const uint32_t*)(p + 8);
                af[i][3] = *(const uint32_t*)(p + 8 * PITCH + 8);
            }
#pragma unroll
            for (int j = 0; j < 4; j++) {
                const __nv_bfloat16* p = bs + (wn0 + j * 8 + g) * PITCH + ks + tig * 2;
                bf[j][0] = *(const uint32_t*)p;
                bf[j][1] = *(const uint32_t*)(p + 8);
            }
#pragma unroll
            for (int i = 0; i < 4; i++)
#pragma unroll
                for (int j = 0; j < 4; j++)
                    MMA16816(acc[i][j], af[i], bf[j]);
        }
        __syncthreads();
    }

    // ---- epilogue ----
    const int rowBase = blockIdx.y * 128 + wm0 + g;
    const int colBase = blockIdx.x * 128 + wn0 + tig * 2;
    if (spl) {
        __nv_bfloat16* sp = spl + (long long)z * sSpl;
#pragma unroll
        for (int i = 0; i < 4; i++)
#pragma unroll
            for (int rr = 0; rr < 2; rr++) {
                const int row = rowBase + i * 16 + rr * 8;
                __nv_bfloat16* rp = sp + (long long)row * splPitch + splColOff;
#pragma unroll
                for (int j = 0; j < 4; j++) {
                    const int col = colBase + j * 8;
                    float v0 = acc[i][j][rr * 2], v1 = acc[i][j][rr * 2 + 1];
                    __nv_bfloat16 h0 = __float2bfloat16(v0), h1 = __float2bfloat16(v1);
                    __nv_bfloat16 l0 = __float2bfloat16(v0 - __bfloat162float(h0));
                    __nv_bfloat16 l1 = __float2bfloat16(v1 - __bfloat162float(h1));
                    __nv_bfloat162 ph; ph.x = h0; ph.y = h1;
                    __nv_bfloat162 pl; pl.x = l0; pl.y = l1;
                    *(__nv_bfloat162*)(rp + col)            = ph;
                    *(__nv_bfloat162*)(rp + splK + col)     = pl;
                    *(__nv_bfloat162*)(rp + 2 * splK + col) = ph;
                }
            }
    } else {
        float* Cb = C + (long long)z * sC;
#pragma unroll
        for (int i = 0; i < 4; i++)
#pragma unroll
            for (int rr = 0; rr < 2; rr++) {
                const int row = rowBase + i * 16 + rr * 8;
                float* rp = Cb + (long long)row * ldc;
#pragma unroll
                for (int j = 0; j < 4; j++) {
                    const int col = colBase + j * 8;
                    float v0 = acc[i][j][rr * 2], v1 = acc[i][j][rr * 2 + 1];
                    if (bias) { v0 += bias[col]; v1 += bias[col + 1]; }
                    if (relu) { v0 = fmaxf(v0, 0.f); v1 = fmaxf(v1, 0.f); }
                    float2 v; v.x = v0; v.y = v1;
                    *(float2*)(rp + col) = v;
                }
            }
    }
#undef LOAD_STAGE
}

// ---------------- prep / fused elementwise kernels ----------------------------

__device__ __forceinline__ void split3(float v, __nv_bfloat16& hi, __nv_bfloat16& lo) {
    hi = __float2bfloat16(v);
    lo = __float2bfloat16(v - __bfloat162float(hi));
}

// weights: dst[R,3K] = [hi | hi | lo]
__global__ void k_splitW(const float* __restrict__ src, __nv_bfloat16* __restrict__ dst,
                         int K, int total)
{
    int i = blockIdx.x * 256 + threadIdx.x;
    if (i >= total) return;
    int r = i / K, c = i - r * K;
    __nv_bfloat16 hi, lo; split3(src[i], hi, lo);
    __nv_bfloat16* d = dst + (long long)r * 3 * K;
    d[c] = hi; d[K + c] = hi; d[2 * K + c] = lo;
}

// adjacency (0/1 exact): dst[b][r][c] = dst[b][r][256+c] = bf16(src)
__global__ void k_adjprep(const float* __restrict__ so, const float* __restrict__ si)
{
    int i = blockIdx.x * 256 + threadIdx.x;      // < 32*256*256
    int br = i >> 8, c = i & 255;
    __nv_bfloat16 vo = __float2bfloat16(so[i]);
    __nv_bfloat16 vi = __float2bfloat16(si[i]);
    g_adjO[(long long)br * 512 + c] = vo;  g_adjO[(long long)br * 512 + 256 + c] = vo;
    g_adjI[(long long)br * 512 + c] = vi;  g_adjI[(long long)br * 512 + 256 + c] = vi;
}

// h = annotation @ anno_W; also write split g_hp [hi|lo|hi]
__global__ void k_embed(const float* __restrict__ anno, const float* __restrict__ W)
{
    int r = blockIdx.x;
    __shared__ float arow[ANNO_];
    if (threadIdx.x < ANNO_) arow[threadIdx.x] = anno[r * ANNO_ + threadIdx.x];
    __syncthreads();
    for (int e = threadIdx.x; e < E_; e += blockDim.x) {
        float s = 0.f;
#pragma unroll
        for (int k = 0; k < ANNO_; k++) s = fmaf(arow[k], W[k * E_ + e], s);
        g_h[(long long)r * E_ + e] = s;
        __nv_bfloat16 hi, lo; split3(s, hi, lo);
        __nv_bfloat16* hp = g_hp + (long long)r * 3072;
        hp[e] = hi; hp[1024 + e] = lo; hp[2048 + e] = hi;
    }
}

// per-batch transpose-split: g_ht[b][e][n]=hi(h[b][n][e]), [e][256+n]=lo
__global__ void k_transpose()
{
    __shared__ float t[32][33];
    int e0 = blockIdx.x * 32, n0 = blockIdx.y * 32, b = blockIdx.z;
    int tx = threadIdx.x, ty = threadIdx.y;   // 32 x 8
#pragma unroll
    for (int j = 0; j < 32; j += 8)
        t[ty + j][tx] = g_h[((long long)b * 256 + n0 + ty + j) * 1024 + e0 + tx];
    __syncthreads();
#pragma unroll
    for (int j = 0; j < 32; j += 8) {
        int e = e0 + ty + j;
        float v = t[tx][ty + j];
        __nv_bfloat16 hi, lo; split3(v, hi, lo);
        __nv_bfloat16* rp = g_ht + ((long long)b * 1024 + e) * 512;
        rp[n0 + tx] = hi; rp[256 + n0 + tx] = lo;
    }
}

__device__ __forceinline__ float sigmoidf_(float x) { return 1.f / (1.f + expf(-x)); }

// encoder GRU update: g_h (f32, in place) + g_hp split
__global__ void k_gru()
{
    long long idx = (long long)blockIdx.x * 256 + threadIdx.x;  // r*1024 + e
    int r = (int)(idx >> 10);
    int e = (int)(idx & 1023);
    const float* gi = g_gi + (long long)r * 3072;
    const float* gh = g_gh + (long long)r * 3072;
    float rr = sigmoidf_(gi[e] + gh[e]);
    float zz = sigmoidf_(gi[1024 + e] + gh[1024 + e]);
    float nn = tanhf(gi[2048 + e] + rr * gh[2048 + e]);
    float hnew = (1.f - zz) * nn + zz * g_h[idx];
    g_h[idx] = hnew;
    __nv_bfloat16 hi, lo; split3(hnew, hi, lo);
    __nv_bfloat16* hp = g_hp + (long long)r * 3072;
    hp[e] = hi; hp[1024 + e] = lo; hp[2048 + e] = hi;
}

__global__ void k_vnf(const float* __restrict__ vnow, const float* __restrict__ vall,
                      const float* __restrict__ Wn, const float* __restrict__ Wa)
{
    int b = blockIdx.x, d = threadIdx.x;
    float sn = 0.f, sa = 0.f;
#pragma unroll
    for (int k = 0; k < 16; k++) {
        sn = fmaf(vnow[b * 16 + k], Wn[k * 64 + d], sn);
        sa = fmaf(vall[b * 16 + k], Wa[k * 64 + d], sa);
    }
    g_vn[b * 64 + d] = sn;
    g_va[b * 64 + d] = sa;
}

// concat' = split([enc_out | npos | va | vn]) into g_cp [hi|lo|hi] pitch 3648
__global__ void k_concat(const int* __restrict__ from_node, const float* __restrict__ pos_enc)
{
    int r = blockIdx.x, b = r >> 8;
    __nv_bfloat16* dst = g_cp + (long long)r * 3648;
    const float* hs = g_h + (long long)r * E_;
    for (int i = threadIdx.x; i < E_; i += blockDim.x) {
        __nv_bfloat16 hi, lo; split3(hs[i], hi, lo);
        dst[i] = hi; dst[1216 + i] = lo; dst[2432 + i] = hi;
    }
    int fn = from_node[b];
    for (int i = threadIdx.x; i < 64; i += blockDim.x) {
        float v0 = pos_enc[fn * 64 + i], v1 = g_va[b * 64 + i], v2 = g_vn[b * 64 + i];
        __nv_bfloat16 hi, lo;
        split3(v0, hi, lo); dst[1024 + i] = hi; dst[2240 + i] = lo; dst[3456 + i] = hi;
        split3(v1, hi, lo); dst[1088 + i] = hi; dst[2304 + i] = lo; dst[3520 + i] = hi;
        split3(v2, hi, lo); dst[1152 + i] = hi; dst[2368 + i] = lo; dst[3584 + i] = hi;
    }
}

// decoder GRU (h0=0 => gh=bhh): hidden f32 to d_out + split g_hidp
__global__ void k_decgru(const float* __restrict__ bhh, float* __restrict__ hidden_out)
{
    long long idx = (long long)blockIdx.x * 256 + threadIdx.x;  // r*2048 + e
    int r = (int)(idx >> 11);
    int e = (int)(idx & 2047);
    const float* gi = g_gid + (long long)r * 6144;
    float rr = sigmoidf_(gi[e] + bhh[e]);
    float zz = sigmoidf_(gi[2048 + e] + bhh[2048 + e]);
    float nn = tanhf(gi[4096 + e] + rr * bhh[4096 + e]);
    float hv = (1.f - zz) * nn;
    hidden_out[idx] = hv;
    __nv_bfloat16 hi, lo; split3(hv, hi, lo);
    __nv_bfloat16* hp = g_hidp + (long long)r * 6144;
    hp[e] = hi; hp[2048 + e] = lo; hp[4096 + e] = hi;
}

// thin head: out3 = mid @ W2^T + b2
__global__ void k_out2(const float* __restrict__ W2, const float* __restrict__ b2)
{
    __shared__ float w[3][1024];
    int tid = threadIdx.x;
    for (int i = tid; i < 3 * 1024; i += 256) w[i >> 10][i & 1023] = W2[i];
    __syncthreads();
    int warp = tid >> 5, lane = tid & 31;
    int r = blockIdx.x * 8 + warp;
    const float* m = g_mid + (long long)r * 1024;
    float s0 = 0.f, s1 = 0.f, s2 = 0.f;
    for (int k = lane; k < 1024; k += 32) {
        float mv = m[k];
        s0 = fmaf(mv, w[0][k], s0);
        s1 = fmaf(mv, w[1][k], s1);
        s2 = fmaf(mv, w[2][k], s2);
    }
#pragma unroll
    for (int off = 16; off; off >>= 1) {
        s0 += __shfl_down_sync(0xffffffffu, s0, off);
        s1 += __shfl_down_sync(0xffffffffu, s1, off);
        s2 += __shfl_down_sync(0xffffffffu, s2, off);
    }
    if (lane == 0) {
        g_out3[r * 3 + 0] = s0 + b2[0];
        g_out3[r * 3 + 1] = s1 + b2[1];
        g_out3[r * 3 + 2] = s2 + b2[2];
    }
}

__global__ void k_max()
{
    int b = blockIdx.x;
    __shared__ float sm[256];
    float mx = -INFINITY;
    for (int i = threadIdx.x; i < N_ * AACT_; i += 256)
        mx = fmaxf(mx, g_out3[b * N_ * AACT_ + i]);
    sm[threadIdx.x] = mx;
    __syncthreads();
    for (int s = 128; s; s >>= 1) {
        if (threadIdx.x < s) sm[threadIdx.x] = fmaxf(sm[threadIdx.x], sm[threadIdx.x + s]);
        __syncthreads();
    }
    if (threadIdx.x == 0) g_maxv[b] = sm[0];
}

__global__ void k_final(const int* __restrict__ mask, float* __restrict__ out)
{
    int r = blockIdx.x * 256 + threadIdx.x;
    if (r >= BN_) return;
    int b = r >> 8;
    float mv = g_maxv[b] + 1.f;
    float mf = (mask[r] == 1) ? 1.f : 1e10f;
    out[r]                 = mf * (g_out3[r * 3 + 0] - mv) + 1.f;
    out[BN_ + r * 2 + 0]   = mf * (g_out3[r * 3 + 1] - mv) + 1.f;
    out[BN_ + r * 2 + 1]   = mf * (g_out3[r * 3 + 2] - mv) + 1.f;
}

// ---------------- launcher ----------------------------------------------------
extern "C" void kernel_launch(void* const* d_in, const int* in_sizes, int n_in,
                              void* d_out, int out_size)
{
    const float* annotation = (const float*)d_in[0];
    const float* A_out      = (const float*)d_in[1];
    const float* A_in       = (const float*)d_in[2];
    const int*   from_node  = (const int*)  d_in[3];
    const float* vnf_now    = (const float*)d_in[4];
    const float* vnf_all    = (const float*)d_in[5];
    const int*   mask       = (const int*)  d_in[6];
    const float* anno_W     = (const float*)d_in[7];
    const float* gru_Wih    = (const float*)d_in[8];
    const float* gru_Whh    = (const float*)d_in[9];
    const float* vnf_now_W  = (const float*)d_in[10];
    const float* vnf_all_W  = (const float*)d_in[11];
    const float* dgru_Wih   = (const float*)d_in[12];
    // d_in[13] = dgru_Whh: unused (h0 == 0 -> gh == dgru_bhh exactly)
    const float* dgru_bih   = (const float*)d_in[14];
    const float* dgru_bhh   = (const float*)d_in[15];
    const float* out_W1     = (const float*)d_in[16];
    const float* out_b1     = (const float*)d_in[17];
    const float* out_W2     = (const float*)d_in[18];
    const float* out_b2     = (const float*)d_in[19];
    const float* pos_enc    = (const float*)d_in[20];

    float* out = (float*)d_out;
    float* hidden = out + BN_ + BN_ * 2;

    float *p_gi, *p_gh, *p_gid, *p_mid;
    __nv_bfloat16 *p_Wihp, *p_Whhp, *p_dWihp, *p_W1p, *p_adjO, *p_adjI;
    __nv_bfloat16 *p_ap, *p_hp, *p_ht, *p_cp, *p_hidp;
    cudaGetSymbolAddress((void**)&p_gi, g_gi);
    cudaGetSymbolAddress((void**)&p_gh, g_gh);
    cudaGetSymbolAddress((void**)&p_gid, g_gid);
    cudaGetSymbolAddress((void**)&p_mid, g_mid);
    cudaGetSymbolAddress((void**)&p_Wihp, g_Wihp);
    cudaGetSymbolAddress((void**)&p_Whhp, g_Whhp);
    cudaGetSymbolAddress((void**)&p_dWihp, g_dWihp);
    cudaGetSymbolAddress((void**)&p_W1p, g_W1p);
    cudaGetSymbolAddress((void**)&p_adjO, g_adjO);
    cudaGetSymbolAddress((void**)&p_adjI, g_adjI);
    cudaGetSymbolAddress((void**)&p_ap, g_ap);
    cudaGetSymbolAddress((void**)&p_hp, g_hp);
    cudaGetSymbolAddress((void**)&p_ht, g_ht);
    cudaGetSymbolAddress((void**)&p_cp, g_cp);
    cudaGetSymbolAddress((void**)&p_hidp, g_hidp);

    // ---- prep: weight splits, adjacency, embedding ----
    k_splitW<<<(3072 * 2048 + 255) / 256, 256>>>(gru_Wih, p_Wihp, 2048, 3072 * 2048);
    k_splitW<<<(3072 * 1024 + 255) / 256, 256>>>(gru_Whh, p_Whhp, 1024, 3072 * 1024);
    k_splitW<<<(6144 * 1216 + 255) / 256, 256>>>(dgru_Wih, p_dWihp, 1216, 6144 * 1216);
    k_splitW<<<(1024 * 2048 + 255) / 256, 256>>>(out_W1, p_W1p, 2048, 1024 * 2048);
    k_adjprep<<<(B_ * 256 * 256) / 256, 256>>>(A_out, A_in);
    k_embed<<<BN_, 256>>>(annotation, anno_W);

    // ---- T encoder GRU steps ----
    for (int t = 0; t < T_; t++) {
        k_transpose<<<dim3(32, 8, 32), dim3(32, 8)>>>();
        // a_out/a_in = Adj @ h  -> split directly into g_ap ([hi|lo|hi], K=2048)
        gemm_mma<<<dim3(8, 2, 32), 256>>>(
            p_adjO, p_ht, 512, 256LL * 512, 1024LL * 512,
            nullptr, 0, 0, nullptr, 0,
            p_ap, 6144, 2048, 0, 256LL * 6144);
        gemm_mma<<<dim3(8, 2, 32), 256>>>(
            p_adjI, p_ht, 512, 256LL * 512, 1024LL * 512,
            nullptr, 0, 0, nullptr, 0,
            p_ap, 6144, 2048, 1024, 256LL * 6144);
        // gi = a' @ Wih'^T   [8192,3072] K'=6144
        gemm_mma<<<dim3(24, 64, 1), 256>>>(
            p_ap, p_Wihp, 6144, 0, 0,
            p_gi, 3072, 0, nullptr, 0, nullptr, 0, 0, 0, 0);
        // gh = h' @ Whh'^T   [8192,3072] K'=3072
        gemm_mma<<<dim3(24, 64, 1), 256>>>(
            p_hp, p_Whhp, 3072, 0, 0,
            p_gh, 3072, 0, nullptr, 0, nullptr, 0, 0, 0, 0);
        k_gru<<<BN_ * E_ / 256, 256>>>();
    }

    // ---- decoder ----
    k_vnf<<<B_, 64>>>(vnf_now, vnf_all, vnf_now_W, vnf_all_W);
    k_concat<<<BN_, 256>>>(from_node, pos_enc);
    // gi_dec = concat' @ dWih'^T + bih   [8192,6144] K'=3648
    gemm_mma<<<dim3(48, 64, 1), 256>>>(
        p_cp, p_dWihp, 3648, 0, 0,
        p_gid, 6144, 0, dgru_bih, 0, nullptr, 0, 0, 0, 0);
    k_decgru<<<BN_ * 2 * E_ / 256, 256>>>(dgru_bhh, hidden);
    // mid = relu(hidden' @ W1'^T + b1)   [8192,1024] K'=6144
    gemm_mma<<<dim3(8, 64, 1), 256>>>(
        p_hidp, p_W1p, 6144, 0, 0,
        p_mid, 1024, 0, out_b1, 1, nullptr, 0, 0, 0, 0);

    // ---- head ----
    k_out2<<<BN_ / 8, 256>>>(out_W2, out_b2);
    k_max<<<B_, 256>>>();
    k_final<<<BN_ / 256, 256>>>(mask, out);
}

// round 8
// speedup vs baseline: 3.1345x; 1.4919x over previous
#include <cuda_runtime.h>
#include <cuda_bf16.h>
#include <math.h>
#include <stdint.h>

// Problem constants
#define B_    32
#define N_    256
#define E_    1024
#define T_    5
#define ANNO_ 18
#define AACT_ 3
#define BN_   8192
#define DEC_IN_ 1216   // E + ND + 2*VD

// ---------------- scratch (static device globals; no allocation) -------------
__device__ float g_h  [BN_ * E_];          // encoder hidden  [8192,1024]
__device__ float g_gi [BN_ * 3 * E_];      // encoder gi      [8192,3072]
__device__ float g_gh [BN_ * 3 * E_];      // encoder gh      [8192,3072]
__device__ float g_gid[BN_ * 6 * E_];      // decoder gi      [8192,6144]
__device__ float g_mid[BN_ * E_];          // relu layer      [8192,1024]
__device__ float g_out3[BN_ * AACT_];
__device__ float g_vn[B_ * 64];
__device__ float g_va[B_ * 64];
__device__ float g_maxv[B_];

// bf16 split operands (merged-K layouts)
__device__ __align__(256) __nv_bfloat16 g_Wihp [3072 * 6144];    // [hi|hi|lo] K=2048
__device__ __align__(256) __nv_bfloat16 g_Whhp [3072 * 3072];    // [hi|hi|lo] K=1024
__device__ __align__(256) __nv_bfloat16 g_dWihp[6144 * 3648];    // [hi|hi|lo] K=1216
__device__ __align__(256) __nv_bfloat16 g_W1p  [1024 * 6144];    // [hi|hi|lo] K=2048
__device__ __align__(256) __nv_bfloat16 g_adjO [B_ * 256 * 512]; // [A|A] exact
__device__ __align__(256) __nv_bfloat16 g_adjI [B_ * 256 * 512];
__device__ __align__(256) __nv_bfloat16 g_ap   [BN_ * 6144];     // a'  [hi|lo|hi] K=2048
__device__ __align__(256) __nv_bfloat16 g_hp   [BN_ * 3072];     // h'  [hi|lo|hi] K=1024
__device__ __align__(256) __nv_bfloat16 g_ht   [B_ * 1024 * 512];// h^T [hi|lo]    K=256x2
__device__ __align__(256) __nv_bfloat16 g_cp   [BN_ * 3648];     // concat' [hi|lo|hi]
__device__ __align__(256) __nv_bfloat16 g_hidp [BN_ * 6144];     // hidden' [hi|lo|hi]

// ---------------- helpers -----------------------------------------------------
__device__ __forceinline__ uint32_t s2u(const void* p) {
    uint32_t a;
    asm("{ .reg .u64 t; cvta.to.shared.u64 t, %1; cvt.u32.u64 %0, t; }" : "=r"(a) : "l"(p));
    return a;
}
__device__ __forceinline__ uint64_t g2u(const void* p) {
    uint64_t a;
    asm("cvta.to.global.u64 %0, %1;" : "=l"(a) : "l"(p));
    return a;
}

#define CP_ASYNC16(smem_u32, gptr64) \
    asm volatile("cp.async.cg.shared.global [%0], [%1], 16;" :: "r"(smem_u32), "l"(gptr64))
#define CP_COMMIT() asm volatile("cp.async.commit_group;" ::: "memory")
#define CP_WAIT(n)  asm volatile("cp.async.wait_group %0;" :: "n"(n) : "memory")

#define LDSM4(r0, r1, r2, r3, addr)                                           \
    asm volatile("ldmatrix.sync.aligned.m8n8.x4.shared.b16 {%0,%1,%2,%3}, [%4];" \
                 : "=r"(r0), "=r"(r1), "=r"(r2), "=r"(r3) : "r"(addr))

#define MMA16816(d, a, b)                                                     \
    asm volatile(                                                             \
        "mma.sync.aligned.m16n8k16.row.col.f32.bf16.bf16.f32 "                \
        "{%0,%1,%2,%3}, {%4,%5,%6,%7}, {%8,%9}, {%0,%1,%2,%3};"               \
        : "+f"((d)[0]), "+f"((d)[1]), "+f"((d)[2]), "+f"((d)[3])              \
        : "r"((a)[0]), "r"((a)[1]), "r"((a)[2]), "r"((a)[3]),                 \
          "r"((b)[0]), "r"((b)[1]))

// ---------------- mma.sync GEMM: C[M,N] = A[M,K'] * B[N,K']^T -----------------
// A,B bf16 row-major K-major. CTA tile 128x128, BK=64 (128B rows), 8 warps
// (warp 64x32). XOR-swizzled SMEM (chunk ^ row&7) + ldmatrix.x4 fragments.
// 3-stage cp.async pipeline, 96KB dynamic smem, 2 CTA/SM.
// Epilogue: spl==null -> f32 (+bias)(+relu) into C;
//           spl!=null -> 3-way bf16 split [hi|lo|hi], pitch splPitch, section
//                        width splK, column offset splColOff.
#define STAGE_BYTES 32768      // A 16KB + B 16KB
#define B_OFF       16384
#define SMEM_TOTAL_GEMM (3 * STAGE_BYTES)

__global__ __launch_bounds__(256, 2)
void gemm_mma(const __nv_bfloat16* __restrict__ A, const __nv_bfloat16* __restrict__ Bm,
              int Kp, long long sA, long long sB,
              float* __restrict__ C, int ldc, long long sC,
              const float* __restrict__ bias, int relu,
              __nv_bfloat16* __restrict__ spl, int splPitch, int splK, int splColOff,
              long long sSpl)
{
    extern __shared__ char smem[];
    const uint32_t smb = s2u(smem);

    const int tid  = threadIdx.x;
    const int wid  = tid >> 5, lane = tid & 31;
    const int g    = lane >> 2, tig = lane & 3;
    const int wm0  = (wid & 1) * 64;
    const int wn0  = (wid >> 1) * 32;
    const int z    = blockIdx.z;

    const __nv_bfloat16* Ab = A  + (long long)z * sA + (long long)(blockIdx.y * 128) * Kp;
    const __nv_bfloat16* Bb = Bm + (long long)z * sB + (long long)(blockIdx.x * 128) * Kp;

    // ---- cp.async coords: 1024 16B chunks per operand per stage, 4/thread ----
    const int rbase = tid >> 3;            // 0..31
    const int ch    = tid & 7;             // 16B chunk within 128B row
    uint64_t gA[4], gB[4];
    uint32_t sAo[4], sBo[4];
#pragma unroll
    for (int i = 0; i < 4; i++) {
        const int r = rbase + 32 * i;
        gA[i] = g2u((const char*)Ab + (long long)r * (Kp * 2) + ch * 16);
        gB[i] = g2u((const char*)Bb + (long long)r * (Kp * 2) + ch * 16);
        const uint32_t sw = (uint32_t)((ch ^ (r & 7)) << 4);
        sAo[i] = smb + r * 128 + sw;
        sBo[i] = smb + B_OFF + r * 128 + sw;
    }

#define LOAD_STAGE(s, idx)                                                 \
    do {                                                                   \
        const long long kB = (long long)(idx) * 128;                       \
        const uint32_t so = (uint32_t)(s) * STAGE_BYTES;                   \
        CP_ASYNC16(sAo[0] + so, gA[0] + kB);                               \
        CP_ASYNC16(sAo[1] + so, gA[1] + kB);                               \
        CP_ASYNC16(sAo[2] + so, gA[2] + kB);                               \
        CP_ASYNC16(sAo[3] + so, gA[3] + kB);                               \
        CP_ASYNC16(sBo[0] + so, gB[0] + kB);                               \
        CP_ASYNC16(sBo[1] + so, gB[1] + kB);                               \
        CP_ASYNC16(sBo[2] + so, gB[2] + kB);                               \
        CP_ASYNC16(sBo[3] + so, gB[3] + kB);                               \
    } while (0)

    // ---- ldmatrix per-lane constants ----
    const int xorL = lane & 7;
    const int cA   = lane >> 4;            // 0/1: k-halves of 16x16 A matrices
    const int cB   = (lane >> 3) & 1;      // 0/1: k-halves of B matrices
    uint32_t aoff[4], boff[2];
#pragma unroll
    for (int i = 0; i < 4; i++)
        aoff[i] = (uint32_t)(wm0 + i * 16 + (lane & 15)) * 128;
#pragma unroll
    for (int jp = 0; jp < 2; jp++)
        boff[jp] = (uint32_t)(wn0 + jp * 16 + (lane & 7) + ((lane & 16) >> 1)) * 128 + B_OFF;

    float acc[4][4][4];
#pragma unroll
    for (int i = 0; i < 4; i++)
#pragma unroll
        for (int j = 0; j < 4; j++)
#pragma unroll
            for (int c = 0; c < 4; c++) acc[i][j][c] = 0.f;

    const int nIter = Kp >> 6;

    // prologue: stages 0,1
    LOAD_STAGE(0, 0); CP_COMMIT();
    if (nIter > 1) LOAD_STAGE(1, 1);
    CP_COMMIT();

    int stage = 0;
    for (int it = 0; it < nIter; ++it) {
        CP_WAIT(1);           // stage `it` complete (empty-commit discipline)
        __syncthreads();      // visible to all warps; all done reading it-1

        if (it + 2 < nIter) {
            int ns = stage + 2; if (ns >= 3) ns -= 3;
            LOAD_STAGE(ns, it + 2);
        }
        CP_COMMIT();          // always commit (possibly empty group)

        const uint32_t sAs = smb + stage * STAGE_BYTES;
#pragma unroll
        for (int ks = 0; ks < 4; ks++) {
            const int c2 = ks * 2;
            uint32_t af[4][4], bf[4][2];
#pragma unroll
            for (int i = 0; i < 4; i++) {
                const uint32_t ad = sAs + aoff[i] + (uint32_t)((((c2 + cA) ^ xorL)) << 4);
                LDSM4(af[i][0], af[i][1], af[i][2], af[i][3], ad);
            }
#pragma unroll
            for (int jp = 0; jp < 2; jp++) {
                const uint32_t bd = sAs + boff[jp] + (uint32_t)((((c2 + cB) ^ xorL)) << 4);
                LDSM4(bf[2 * jp][0], bf[2 * jp][1], bf[2 * jp + 1][0], bf[2 * jp + 1][1], bd);
            }
#pragma unroll
            for (int i = 0; i < 4; i++)
#pragma unroll
                for (int j = 0; j < 4; j++)
                    MMA16816(acc[i][j], af[i], bf[j]);
        }
        if (++stage == 3) stage = 0;
    }

    // ---- epilogue ----
    const int rowBase = blockIdx.y * 128 + wm0 + g;
    const int colBase = blockIdx.x * 128 + wn0 + tig * 2;
    if (spl) {
        __nv_bfloat16* sp = spl + (long long)z * sSpl;
#pragma unroll
        for (int i = 0; i < 4; i++)
#pragma unroll
            for (int rr = 0; rr < 2; rr++) {
                const int row = rowBase + i * 16 + rr * 8;
                __nv_bfloat16* rp = sp + (long long)row * splPitch + splColOff;
#pragma unroll
                for (int j = 0; j < 4; j++) {
                    const int col = colBase + j * 8;
                    float v0 = acc[i][j][rr * 2], v1 = acc[i][j][rr * 2 + 1];
                    __nv_bfloat16 h0 = __float2bfloat16(v0), h1 = __float2bfloat16(v1);
                    __nv_bfloat16 l0 = __float2bfloat16(v0 - __bfloat162float(h0));
                    __nv_bfloat16 l1 = __float2bfloat16(v1 - __bfloat162float(h1));
                    __nv_bfloat162 ph; ph.x = h0; ph.y = h1;
                    __nv_bfloat162 pl; pl.x = l0; pl.y = l1;
                    *(__nv_bfloat162*)(rp + col)            = ph;
                    *(__nv_bfloat162*)(rp + splK + col)     = pl;
                    *(__nv_bfloat162*)(rp + 2 * splK + col) = ph;
                }
            }
    } else {
        float* Cb = C + (long long)z * sC;
#pragma unroll
        for (int i = 0; i < 4; i++)
#pragma unroll
            for (int rr = 0; rr < 2; rr++) {
                const int row = rowBase + i * 16 + rr * 8;
                float* rp = Cb + (long long)row * ldc;
#pragma unroll
                for (int j = 0; j < 4; j++) {
                    const int col = colBase + j * 8;
                    float v0 = acc[i][j][rr * 2], v1 = acc[i][j][rr * 2 + 1];
                    if (bias) { v0 += bias[col]; v1 += bias[col + 1]; }
                    if (relu) { v0 = fmaxf(v0, 0.f); v1 = fmaxf(v1, 0.f); }
                    float2 v; v.x = v0; v.y = v1;
                    *(float2*)(rp + col) = v;
                }
            }
    }
#undef LOAD_STAGE
}

// ---------------- prep / fused elementwise kernels ----------------------------

__device__ __forceinline__ void split3(float v, __nv_bfloat16& hi, __nv_bfloat16& lo) {
    hi = __float2bfloat16(v);
    lo = __float2bfloat16(v - __bfloat162float(hi));
}

// weights: dst[R,3K] = [hi | hi | lo]
__global__ void k_splitW(const float* __restrict__ src, __nv_bfloat16* __restrict__ dst,
                         int K, int total)
{
    int i = blockIdx.x * 256 + threadIdx.x;
    if (i >= total) return;
    int r = i / K, c = i - r * K;
    __nv_bfloat16 hi, lo; split3(src[i], hi, lo);
    __nv_bfloat16* d = dst + (long long)r * 3 * K;
    d[c] = hi; d[K + c] = hi; d[2 * K + c] = lo;
}

// adjacency (0/1 exact): dst[b][r][c] = dst[b][r][256+c] = bf16(src)
__global__ void k_adjprep(const float* __restrict__ so, const float* __restrict__ si)
{
    int i = blockIdx.x * 256 + threadIdx.x;      // < 32*256*256
    int br = i >> 8, c = i & 255;
    __nv_bfloat16 vo = __float2bfloat16(so[i]);
    __nv_bfloat16 vi = __float2bfloat16(si[i]);
    g_adjO[(long long)br * 512 + c] = vo;  g_adjO[(long long)br * 512 + 256 + c] = vo;
    g_adjI[(long long)br * 512 + c] = vi;  g_adjI[(long long)br * 512 + 256 + c] = vi;
}

// h = annotation @ anno_W; also write split g_hp [hi|lo|hi]
__global__ void k_embed(const float* __restrict__ anno, const float* __restrict__ W)
{
    int r = blockIdx.x;
    __shared__ float arow[ANNO_];
    if (threadIdx.x < ANNO_) arow[threadIdx.x] = anno[r * ANNO_ + threadIdx.x];
    __syncthreads();
    for (int e = threadIdx.x; e < E_; e += blockDim.x) {
        float s = 0.f;
#pragma unroll
        for (int k = 0; k < ANNO_; k++) s = fmaf(arow[k], W[k * E_ + e], s);
        g_h[(long long)r * E_ + e] = s;
        __nv_bfloat16 hi, lo; split3(s, hi, lo);
        __nv_bfloat16* hp = g_hp + (long long)r * 3072;
        hp[e] = hi; hp[1024 + e] = lo; hp[2048 + e] = hi;
    }
}

// per-batch transpose-split: g_ht[b][e][n]=hi(h[b][n][e]), [e][256+n]=lo
__global__ void k_transpose()
{
    __shared__ float t[32][33];
    int e0 = blockIdx.x * 32, n0 = blockIdx.y * 32, b = blockIdx.z;
    int tx = threadIdx.x, ty = threadIdx.y;   // 32 x 8
#pragma unroll
    for (int j = 0; j < 32; j += 8)
        t[ty + j][tx] = g_h[((long long)b * 256 + n0 + ty + j) * 1024 + e0 + tx];
    __syncthreads();
#pragma unroll
    for (int j = 0; j < 32; j += 8) {
        int e = e0 + ty + j;
        float v = t[tx][ty + j];
        __nv_bfloat16 hi, lo; split3(v, hi, lo);
        __nv_bfloat16* rp = g_ht + ((long long)b * 1024 + e) * 512;
        rp[n0 + tx] = hi; rp[256 + n0 + tx] = lo;
    }
}

__device__ __forceinline__ float sigmoidf_(float x) { return 1.f / (1.f + expf(-x)); }

// encoder GRU update: g_h (f32, in place) + g_hp split
__global__ void k_gru()
{
    long long idx = (long long)blockIdx.x * 256 + threadIdx.x;  // r*1024 + e
    int r = (int)(idx >> 10);
    int e = (int)(idx & 1023);
    const float* gi = g_gi + (long long)r * 3072;
    const float* gh = g_gh + (long long)r * 3072;
    float rr = sigmoidf_(gi[e] + gh[e]);
    float zz = sigmoidf_(gi[1024 + e] + gh[1024 + e]);
    float nn = tanhf(gi[2048 + e] + rr * gh[2048 + e]);
    float hnew = (1.f - zz) * nn + zz * g_h[idx];
    g_h[idx] = hnew;
    __nv_bfloat16 hi, lo; split3(hnew, hi, lo);
    __nv_bfloat16* hp = g_hp + (long long)r * 3072;
    hp[e] = hi; hp[1024 + e] = lo; hp[2048 + e] = hi;
}

__global__ void k_vnf(const float* __restrict__ vnow, const float* __restrict__ vall,
                      const float* __restrict__ Wn, const float* __restrict__ Wa)
{
    int b = blockIdx.x, d = threadIdx.x;
    float sn = 0.f, sa = 0.f;
#pragma unroll
    for (int k = 0; k < 16; k++) {
        sn = fmaf(vnow[b * 16 + k], Wn[k * 64 + d], sn);
        sa = fmaf(vall[b * 16 + k], Wa[k * 64 + d], sa);
    }
    g_vn[b * 64 + d] = sn;
    g_va[b * 64 + d] = sa;
}

// concat' = split([enc_out | npos | va | vn]) into g_cp [hi|lo|hi] pitch 3648
__global__ void k_concat(const int* __restrict__ from_node, const float* __restrict__ pos_enc)
{
    int r = blockIdx.x, b = r >> 8;
    __nv_bfloat16* dst = g_cp + (long long)r * 3648;
    const float* hs = g_h + (long long)r * E_;
    for (int i = threadIdx.x; i < E_; i += blockDim.x) {
        __nv_bfloat16 hi, lo; split3(hs[i], hi, lo);
        dst[i] = hi; dst[1216 + i] = lo; dst[2432 + i] = hi;
    }
    int fn = from_node[b];
    for (int i = threadIdx.x; i < 64; i += blockDim.x) {
        float v0 = pos_enc[fn * 64 + i], v1 = g_va[b * 64 + i], v2 = g_vn[b * 64 + i];
        __nv_bfloat16 hi, lo;
        split3(v0, hi, lo); dst[1024 + i] = hi; dst[2240 + i] = lo; dst[3456 + i] = hi;
        split3(v1, hi, lo); dst[1088 + i] = hi; dst[2304 + i] = lo; dst[3520 + i] = hi;
        split3(v2, hi, lo); dst[1152 + i] = hi; dst[2368 + i] = lo; dst[3584 + i] = hi;
    }
}

// decoder GRU (h0=0 => gh=bhh): hidden f32 to d_out + split g_hidp
__global__ void k_decgru(const float* __restrict__ bhh, float* __restrict__ hidden_out)
{
    long long idx = (long long)blockIdx.x * 256 + threadIdx.x;  // r*2048 + e
    int r = (int)(idx >> 11);
    int e = (int)(idx & 2047);
    const float* gi = g_gid + (long long)r * 6144;
    float rr = sigmoidf_(gi[e] + bhh[e]);
    float zz = sigmoidf_(gi[2048 + e] + bhh[2048 + e]);
    float nn = tanhf(gi[4096 + e] + rr * bhh[4096 + e]);
    float hv = (1.f - zz) * nn;
    hidden_out[idx] = hv;
    __nv_bfloat16 hi, lo; split3(hv, hi, lo);
    __nv_bfloat16* hp = g_hidp + (long long)r * 6144;
    hp[e] = hi; hp[2048 + e] = lo; hp[4096 + e] = hi;
}

// thin head: out3 = mid @ W2^T + b2
__global__ void k_out2(const float* __restrict__ W2, const float* __restrict__ b2)
{
    __shared__ float w[3][1024];
    int tid = threadIdx.x;
    for (int i = tid; i < 3 * 1024; i += 256) w[i >> 10][i & 1023] = W2[i];
    __syncthreads();
    int warp = tid >> 5, lane = tid & 31;
    int r = blockIdx.x * 8 + warp;
    const float* m = g_mid + (long long)r * 1024;
    float s0 = 0.f, s1 = 0.f, s2 = 0.f;
    for (int k = lane; k < 1024; k += 32) {
        float mv = m[k];
        s0 = fmaf(mv, w[0][k], s0);
        s1 = fmaf(mv, w[1][k], s1);
        s2 = fmaf(mv, w[2][k], s2);
    }
#pragma unroll
    for (int off = 16; off; off >>= 1) {
        s0 += __shfl_down_sync(0xffffffffu, s0, off);
        s1 += __shfl_down_sync(0xffffffffu, s1, off);
        s2 += __shfl_down_sync(0xffffffffu, s2, off);
    }
    if (lane == 0) {
        g_out3[r * 3 + 0] = s0 + b2[0];
        g_out3[r * 3 + 1] = s1 + b2[1];
        g_out3[r * 3 + 2] = s2 + b2[2];
    }
}

__global__ void k_max()
{
    int b = blockIdx.x;
    __shared__ float sm[256];
    float mx = -INFINITY;
    for (int i = threadIdx.x; i < N_ * AACT_; i += 256)
        mx = fmaxf(mx, g_out3[b * N_ * AACT_ + i]);
    sm[threadIdx.x] = mx;
    __syncthreads();
    for (int s = 128; s; s >>= 1) {
        if (threadIdx.x < s) sm[threadIdx.x] = fmaxf(sm[threadIdx.x], sm[threadIdx.x + s]);
        __syncthreads();
    }
    if (threadIdx.x == 0) g_maxv[b] = sm[0];
}

__global__ void k_final(const int* __restrict__ mask, float* __restrict__ out)
{
    int r = blockIdx.x * 256 + threadIdx.x;
    if (r >= BN_) return;
    int b = r >> 8;
    float mv = g_maxv[b] + 1.f;
    float mf = (mask[r] == 1) ? 1.f : 1e10f;
    out[r]                 = mf * (g_out3[r * 3 + 0] - mv) + 1.f;
    out[BN_ + r * 2 + 0]   = mf * (g_out3[r * 3 + 1] - mv) + 1.f;
    out[BN_ + r * 2 + 1]   = mf * (g_out3[r * 3 + 2] - mv) + 1.f;
}

// ---------------- launcher ----------------------------------------------------
extern "C" void kernel_launch(void* const* d_in, const int* in_sizes, int n_in,
                              void* d_out, int out_size)
{
    const float* annotation = (const float*)d_in[0];
    const float* A_out      = (const float*)d_in[1];
    const float* A_in       = (const float*)d_in[2];
    const int*   from_node  = (const int*)  d_in[3];
    const float* vnf_now    = (const float*)d_in[4];
    const float* vnf_all    = (const float*)d_in[5];
    const int*   mask       = (const int*)  d_in[6];
    const float* anno_W     = (const float*)d_in[7];
    const float* gru_Wih    = (const float*)d_in[8];
    const float* gru_Whh    = (const float*)d_in[9];
    const float* vnf_now_W  = (const float*)d_in[10];
    const float* vnf_all_W  = (const float*)d_in[11];
    const float* dgru_Wih   = (const float*)d_in[12];
    // d_in[13] = dgru_Whh: unused (h0 == 0 -> gh == dgru_bhh exactly)
    const float* dgru_bih   = (const float*)d_in[14];
    const float* dgru_bhh   = (const float*)d_in[15];
    const float* out_W1     = (const float*)d_in[16];
    const float* out_b1     = (const float*)d_in[17];
    const float* out_W2     = (const float*)d_in[18];
    const float* out_b2     = (const float*)d_in[19];
    const float* pos_enc    = (const float*)d_in[20];

    float* out = (float*)d_out;
    float* hidden = out + BN_ + BN_ * 2;

    cudaFuncSetAttribute(gemm_mma, cudaFuncAttributeMaxDynamicSharedMemorySize,
                         SMEM_TOTAL_GEMM);

    float *p_gi, *p_gh, *p_gid, *p_mid;
    __nv_bfloat16 *p_Wihp, *p_Whhp, *p_dWihp, *p_W1p, *p_adjO, *p_adjI;
    __nv_bfloat16 *p_ap, *p_hp, *p_ht, *p_cp, *p_hidp;
    cudaGetSymbolAddress((void**)&p_gi, g_gi);
    cudaGetSymbolAddress((void**)&p_gh, g_gh);
    cudaGetSymbolAddress((void**)&p_gid, g_gid);
    cudaGetSymbolAddress((void**)&p_mid, g_mid);
    cudaGetSymbolAddress((void**)&p_Wihp, g_Wihp);
    cudaGetSymbolAddress((void**)&p_Whhp, g_Whhp);
    cudaGetSymbolAddress((void**)&p_dWihp, g_dWihp);
    cudaGetSymbolAddress((void**)&p_W1p, g_W1p);
    cudaGetSymbolAddress((void**)&p_adjO, g_adjO);
    cudaGetSymbolAddress((void**)&p_adjI, g_adjI);
    cudaGetSymbolAddress((void**)&p_ap, g_ap);
    cudaGetSymbolAddress((void**)&p_hp, g_hp);
    cudaGetSymbolAddress((void**)&p_ht, g_ht);
    cudaGetSymbolAddress((void**)&p_cp, g_cp);
    cudaGetSymbolAddress((void**)&p_hidp, g_hidp);

    // ---- prep: weight splits, adjacency, embedding ----
    k_splitW<<<(3072 * 2048 + 255) / 256, 256>>>(gru_Wih, p_Wihp, 2048, 3072 * 2048);
    k_splitW<<<(3072 * 1024 + 255) / 256, 256>>>(gru_Whh, p_Whhp, 1024, 3072 * 1024);
    k_splitW<<<(6144 * 1216 + 255) / 256, 256>>>(dgru_Wih, p_dWihp, 1216, 6144 * 1216);
    k_splitW<<<(1024 * 2048 + 255) / 256, 256>>>(out_W1, p_W1p, 2048, 1024 * 2048);
    k_adjprep<<<(B_ * 256 * 256) / 256, 256>>>(A_out, A_in);
    k_embed<<<BN_, 256>>>(annotation, anno_W);

    // ---- T encoder GRU steps ----
    for (int t = 0; t < T_; t++) {
        k_transpose<<<dim3(32, 8, 32), dim3(32, 8)>>>();
        // a_out/a_in = Adj @ h  -> split directly into g_ap ([hi|lo|hi], K=2048)
        gemm_mma<<<dim3(8, 2, 32), 256, SMEM_TOTAL_GEMM>>>(
            p_adjO, p_ht, 512, 256LL * 512, 1024LL * 512,
            nullptr, 0, 0, nullptr, 0,
            p_ap, 6144, 2048, 0, 256LL * 6144);
        gemm_mma<<<dim3(8, 2, 32), 256, SMEM_TOTAL_GEMM>>>(
            p_adjI, p_ht, 512, 256LL * 512, 1024LL * 512,
            nullptr, 0, 0, nullptr, 0,
            p_ap, 6144, 2048, 1024, 256LL * 6144);
        // gi = a' @ Wih'^T   [8192,3072] K'=6144
        gemm_mma<<<dim3(24, 64, 1), 256, SMEM_TOTAL_GEMM>>>(
            p_ap, p_Wihp, 6144, 0, 0,
            p_gi, 3072, 0, nullptr, 0, nullptr, 0, 0, 0, 0);
        // gh = h' @ Whh'^T   [8192,3072] K'=3072
        gemm_mma<<<dim3(24, 64, 1), 256, SMEM_TOTAL_GEMM>>>(
            p_hp, p_Whhp, 3072, 0, 0,
            p_gh, 3072, 0, nullptr, 0, nullptr, 0, 0, 0, 0);
        k_gru<<<BN_ * E_ / 256, 256>>>();
    }

    // ---- decoder ----
    k_vnf<<<B_, 64>>>(vnf_now, vnf_all, vnf_now_W, vnf_all_W);
    k_concat<<<BN_, 256>>>(from_node, pos_enc);
    // gi_dec = concat' @ dWih'^T + bih   [8192,6144] K'=3648
    gemm_mma<<<dim3(48, 64, 1), 256, SMEM_TOTAL_GEMM>>>(
        p_cp, p_dWihp, 3648, 0, 0,
        p_gid, 6144, 0, dgru_bih, 0, nullptr, 0, 0, 0, 0);
    k_decgru<<<BN_ * 2 * E_ / 256, 256>>>(dgru_bhh, hidden);
    // mid = relu(hidden' @ W1'^T + b1)   [8192,1024] K'=6144
    gemm_mma<<<dim3(8, 64, 1), 256, SMEM_TOTAL_GEMM>>>(
        p_hidp, p_W1p, 6144, 0, 0,
        p_mid, 1024, 0, out_b1, 1, nullptr, 0, 0, 0, 0);

    // ---- head ----
    k_out2<<<BN_ / 8, 256>>>(out_W2, out_b2);
    k_max<<<B_, 256>>>();
    k_final<<<BN_ / 256, 256>>>(mask, out);
}